// round 1
// baseline (speedup 1.0000x reference)
#include <cuda_runtime.h>
#include <math.h>

// Problem constants
#define B_    2
#define S_    2048
#define HID_  4096
#define H_    32
#define KVH_  8
#define D_    128
#define NREP  (H_/KVH_)                 // 4
#define QKVN  (HID_ + 2*KVH_*D_)        // 6144
#define MTOK  (B_*S_)                   // 4096

// Scratch (static device globals; no runtime allocation allowed)
__device__ float g_qkv[(size_t)MTOK * QKVN];            // [tok][6144]
__device__ float g_q  [(size_t)B_*H_*S_*D_];            // [B][H][S][D]
__device__ float g_k  [(size_t)B_*KVH_*S_*D_];          // [B][KVH][S][D]
__device__ float g_v  [(size_t)B_*KVH_*S_*D_];          // [B][KVH][S][D]
__device__ float g_ao [(size_t)MTOK * H_*D_];           // [B][S][H][D]

// ---------------------------------------------------------------------------
// SGEMM NT: C[M,N] = A[M,K] (row-major) * B[N,K]^T (row-major)
// 128x128 block tile, BK=16, 256 threads, 8x8 microtile.
// ---------------------------------------------------------------------------
__global__ __launch_bounds__(256) void sgemm_nt(
    const float* __restrict__ A, const float* __restrict__ Bm,
    float* __restrict__ C, int M, int N, int K)
{
    const int BM = 128, BN = 128, BK = 16;
    __shared__ float As[BK][BM + 4];
    __shared__ float Bs[BK][BN + 4];

    int tid = threadIdx.x;
    int tx = tid & 15;          // 0..15  (N direction)
    int ty = tid >> 4;          // 0..15  (M direction)
    int m0 = blockIdx.y * BM;
    int n0 = blockIdx.x * BN;

    float acc[8][8];
#pragma unroll
    for (int i = 0; i < 8; i++)
#pragma unroll
        for (int j = 0; j < 8; j++) acc[i][j] = 0.f;

    int lr = tid >> 2;            // 0..63 : row within tile
    int lc = (tid & 3) << 2;      // 0,4,8,12 : col (k) within tile

    for (int k0 = 0; k0 < K; k0 += BK) {
#pragma unroll
        for (int rr = 0; rr < 2; rr++) {
            int r = lr + rr * 64;
            float4 va = *(const float4*)&A[(size_t)(m0 + r) * K + k0 + lc];
            As[lc + 0][r] = va.x; As[lc + 1][r] = va.y;
            As[lc + 2][r] = va.z; As[lc + 3][r] = va.w;
            float4 vb = *(const float4*)&Bm[(size_t)(n0 + r) * K + k0 + lc];
            Bs[lc + 0][r] = vb.x; Bs[lc + 1][r] = vb.y;
            Bs[lc + 2][r] = vb.z; Bs[lc + 3][r] = vb.w;
        }
        __syncthreads();

#pragma unroll
        for (int k = 0; k < BK; k++) {
            float4 a0 = *(const float4*)&As[k][ty * 8];
            float4 a1 = *(const float4*)&As[k][ty * 8 + 4];
            float4 b0 = *(const float4*)&Bs[k][tx * 8];
            float4 b1 = *(const float4*)&Bs[k][tx * 8 + 4];
            float a[8] = {a0.x, a0.y, a0.z, a0.w, a1.x, a1.y, a1.z, a1.w};
            float b[8] = {b0.x, b0.y, b0.z, b0.w, b1.x, b1.y, b1.z, b1.w};
#pragma unroll
            for (int i = 0; i < 8; i++)
#pragma unroll
                for (int j = 0; j < 8; j++)
                    acc[i][j] = fmaf(a[i], b[j], acc[i][j]);
        }
        __syncthreads();
    }

#pragma unroll
    for (int i = 0; i < 8; i++) {
        size_t coff = (size_t)(m0 + ty * 8 + i) * N + n0 + tx * 8;
        *(float4*)&C[coff]     = make_float4(acc[i][0], acc[i][1], acc[i][2], acc[i][3]);
        *(float4*)&C[coff + 4] = make_float4(acc[i][4], acc[i][5], acc[i][6], acc[i][7]);
    }
}

// ---------------------------------------------------------------------------
// RoPE + per-head RMSNorm + scatter into q/k/v attention layouts.
// grid = (H+2*KVH, B*S), block = 128 (one thread per d).
// ---------------------------------------------------------------------------
__global__ __launch_bounds__(128) void rope_norm(
    const float* __restrict__ cosb, const float* __restrict__ sinb,
    const float* __restrict__ qw,   const float* __restrict__ kw)
{
    int tok = blockIdx.y;
    int hh  = blockIdx.x;
    int d   = threadIdx.x;
    int b = tok / S_, s = tok % S_;
    const float* row = g_qkv + (size_t)tok * QKVN;

    if (hh >= H_ + KVH_) {                    // V: straight copy, no rope/norm
        int kv = hh - (H_ + KVH_);
        g_v[(((size_t)b * KVH_ + kv) * S_ + s) * D_ + d] =
            row[H_ * D_ + KVH_ * D_ + kv * D_ + d];
        return;
    }

    float c  = cosb[((size_t)b * S_ + s) * D_ + d];
    float sn = sinb[((size_t)b * S_ + s) * D_ + d];
    int off = (hh < H_) ? hh * D_ : H_ * D_ + (hh - H_) * D_;
    float x  = row[off + d];
    float xr = (d < 64) ? -row[off + d + 64] : row[off + d - 64];
    float y  = x * c + xr * sn;

    float v2 = y * y;
#pragma unroll
    for (int o = 16; o; o >>= 1) v2 += __shfl_xor_sync(0xffffffffu, v2, o);
    __shared__ float red[4];
    if ((d & 31) == 0) red[d >> 5] = v2;
    __syncthreads();
    float tot = red[0] + red[1] + red[2] + red[3];
    float inv = rsqrtf(tot * (1.f / D_) + 1e-6f);
    float w = (hh < H_) ? qw[d] : kw[d];
    float outv = w * y * inv;

    if (hh < H_)
        g_q[(((size_t)b * H_ + hh) * S_ + s) * D_ + d] = outv;
    else
        g_k[(((size_t)b * KVH_ + (hh - H_)) * S_ + s) * D_ + d] = outv;
}

// ---------------------------------------------------------------------------
// Flash attention (fp32, non-causal, online softmax).
// Br=Bc=64, D=128. 256 threads: thread t -> row i = t/4, quarter jq = t%4.
// Each thread owns d in {g*16 + jq*4 .. +3 : g=0..7} (interleaved for
// conflict-free V reads), and score columns j = jj*4+jq (interleaved for
// conflict-free K reads).
// ---------------------------------------------------------------------------
#define BR 64
#define BC 64
#define DP 132     // padded row stride of Q/K/V tiles
#define PP 68      // padded row stride of P tile
#define ATTN_SMEM ((3 * BR * DP + BR * PP) * 4)   // 118784 bytes

__global__ __launch_bounds__(256) void flash_attn(float* __restrict__ AO)
{
    extern __shared__ float sm[];
    float* sQ = sm;
    float* sK = sQ + BR * DP;
    float* sV = sK + BC * DP;
    float* sP = sV + BC * DP;

    int b  = blockIdx.z, h = blockIdx.y;
    int q0 = blockIdx.x * BR;
    int kh = h / NREP;
    const float* Qg = g_q + (((size_t)b * H_ + h) * S_ + q0) * D_;
    const float* Kg = g_k + ((size_t)b * KVH_ + kh) * (size_t)S_ * D_;
    const float* Vg = g_v + ((size_t)b * KVH_ + kh) * (size_t)S_ * D_;

    int tid = threadIdx.x;
    int i  = tid >> 2;      // row 0..63
    int jq = tid & 3;       // 0..3

    // Load Q tile (64 x 128) -> padded smem
    for (int e = tid; e < BR * 32; e += 256) {
        int r = e >> 5, c = e & 31;
        float4 v = ((const float4*)Qg)[r * 32 + c];
        *(float4*)&sQ[r * DP + c * 4] = v;
    }

    float acc[32];
#pragma unroll
    for (int t = 0; t < 32; t++) acc[t] = 0.f;
    float m_i = -1e30f, l_i = 0.f;
    const float scale = 0.08838834764831845f;   // 1/sqrt(128)

    for (int t0 = 0; t0 < S_; t0 += BC) {
        __syncthreads();   // previous tile's sV/sP fully consumed
        for (int e = tid; e < BC * 32; e += 256) {
            int r = e >> 5, c = e & 31;
            *(float4*)&sK[r * DP + c * 4] = ((const float4*)(Kg + (size_t)t0 * D_))[r * 32 + c];
            *(float4*)&sV[r * DP + c * 4] = ((const float4*)(Vg + (size_t)t0 * D_))[r * 32 + c];
        }
        __syncthreads();

        // scores: thread computes 16 columns j = jj*4 + jq of row i
        float sc[16];
#pragma unroll
        for (int jj = 0; jj < 16; jj++) sc[jj] = 0.f;
#pragma unroll 4
        for (int d4 = 0; d4 < 32; d4++) {
            float4 qv = *(const float4*)&sQ[i * DP + d4 * 4];
#pragma unroll
            for (int jj = 0; jj < 16; jj++) {
                int j = jj * 4 + jq;
                float4 kv = *(const float4*)&sK[j * DP + d4 * 4];
                sc[jj] += qv.x * kv.x + qv.y * kv.y + qv.z * kv.z + qv.w * kv.w;
            }
        }

        float mt = -1e30f;
#pragma unroll
        for (int jj = 0; jj < 16; jj++) { sc[jj] *= scale; mt = fmaxf(mt, sc[jj]); }
        mt = fmaxf(mt, __shfl_xor_sync(0xffffffffu, mt, 1));
        mt = fmaxf(mt, __shfl_xor_sync(0xffffffffu, mt, 2));
        float m_new = fmaxf(m_i, mt);
        float corr = __expf(m_i - m_new);

        float ls = 0.f;
#pragma unroll
        for (int jj = 0; jj < 16; jj++) {
            float p = __expf(sc[jj] - m_new);
            ls += p;
            sP[i * PP + jj * 4 + jq] = p;
        }
        ls += __shfl_xor_sync(0xffffffffu, ls, 1);
        ls += __shfl_xor_sync(0xffffffffu, ls, 2);
        l_i = l_i * corr + ls;
        m_i = m_new;
#pragma unroll
        for (int t = 0; t < 32; t++) acc[t] *= corr;
        __syncthreads();   // sP visible to all 4 jq-threads of each row

        // acc[i][d] += sum_j P[i][j] * V[j][d], d = g*16 + jq*4 + c
#pragma unroll 2
        for (int j = 0; j < BC; j++) {
            float pv = sP[i * PP + j];
            const float4* vr = (const float4*)&sV[j * DP + jq * 4];
#pragma unroll
            for (int g = 0; g < 8; g++) {
                float4 vv = vr[g * 4];
                acc[g * 4 + 0] += pv * vv.x;
                acc[g * 4 + 1] += pv * vv.y;
                acc[g * 4 + 2] += pv * vv.z;
                acc[g * 4 + 3] += pv * vv.w;
            }
        }
    }

    float inv = 1.f / l_i;
    float* Og = AO + (((size_t)(b * S_ + q0 + i)) * H_ + h) * (size_t)D_;
#pragma unroll
    for (int g = 0; g < 8; g++) {
        float4 o = make_float4(acc[g * 4 + 0] * inv, acc[g * 4 + 1] * inv,
                               acc[g * 4 + 2] * inv, acc[g * 4 + 3] * inv);
        *(float4*)&Og[g * 16 + jq * 4] = o;
    }
}

// ---------------------------------------------------------------------------
extern "C" void kernel_launch(void* const* d_in, const int* in_sizes, int n_in,
                              void* d_out, int out_size)
{
    const float* hidden = (const float*)d_in[0];
    const float* cosb   = (const float*)d_in[1];
    const float* sinb   = (const float*)d_in[2];
    const float* qkv_w  = (const float*)d_in[3];
    const float* o_w    = (const float*)d_in[4];
    const float* qnw    = (const float*)d_in[5];
    const float* knw    = (const float*)d_in[6];
    float* out = (float*)d_out;

    float *qkvp, *aop;
    cudaGetSymbolAddress((void**)&qkvp, g_qkv);
    cudaGetSymbolAddress((void**)&aop,  g_ao);

    cudaFuncSetAttribute(flash_attn, cudaFuncAttributeMaxDynamicSharedMemorySize,
                         ATTN_SMEM);

    // 1) QKV projection: [4096,6144] = hidden[4096,4096] @ qkv_w[6144,4096]^T
    dim3 g1(QKVN / 128, MTOK / 128);
    sgemm_nt<<<g1, 256>>>(hidden, qkv_w, qkvp, MTOK, QKVN, HID_);

    // 2) RoPE + RMSNorm + layout scatter
    dim3 g2(H_ + 2 * KVH_, MTOK);
    rope_norm<<<g2, 128>>>(cosb, sinb, qnw, knw);

    // 3) Attention
    dim3 g3(S_ / BR, H_, B_);
    flash_attn<<<g3, 256, ATTN_SMEM>>>(aop);

    // 4) O projection: out[4096,4096] = AO[4096,4096] @ o_w[4096,4096]^T
    dim3 g4(HID_ / 128, MTOK / 128);
    sgemm_nt<<<g4, 256>>>(aop, o_w, out, MTOK, HID_, H_ * D_);
}

// round 3
// speedup vs baseline: 1.3731x; 1.3731x over previous
#include <cuda_runtime.h>
#include <cstdint>
#include <math.h>

// Problem constants
#define B_    2
#define S_    2048
#define HID_  4096
#define H_    32
#define KVH_  8
#define D_    128
#define NREP  (H_/KVH_)                 // 4
#define QKVN  (HID_ + 2*KVH_*D_)        // 6144
#define MTOK  (B_*S_)                   // 4096

// Scratch (static device globals; no runtime allocation allowed)
__device__ float g_qkv[(size_t)MTOK * QKVN];            // [tok][6144]
__device__ float g_q  [(size_t)B_*H_*S_*D_];            // [B][H][S][D]
__device__ float g_k  [(size_t)B_*KVH_*S_*D_];          // [B][KVH][S][D]
__device__ float g_v  [(size_t)B_*KVH_*S_*D_];          // [B][KVH][S][D]
__device__ float g_ao [(size_t)MTOK * H_*D_];           // [B][S][H][D]

// ===========================================================================
// tf32 mma.sync GEMM (NT): C[M,N] = A[M,K] * B[N,K]^T, fp32 in/out.
// 128x128 CTA tile, BK=16, 8 warps (2x4), 64x32 warp tile, 3-stage cp.async.
// SMEM layout: [row][k] with stride 20 floats -> conflict-free frag loads.
// ===========================================================================
#define GBM 128
#define GBN 128
#define GBK 16
#define GSTRIDE 20                        // floats per smem row (16 + 4 pad)
#define G_TILE_FLOATS (128 * GSTRIDE)     // 2560 floats = 10240 B
#define G_STAGE_FLOATS (2 * G_TILE_FLOATS)
#define G_NSTAGE 3
#define G_DYN_SMEM (G_NSTAGE * G_STAGE_FLOATS * 4)   // 61440 bytes

__device__ __forceinline__ uint32_t f2tf32(float f) {
    uint32_t r;
    asm("cvt.rna.tf32.f32 %0, %1;" : "=r"(r) : "f"(f));
    return r;
}

__device__ __forceinline__ void mma_tf32(float* c, const uint32_t* a, const uint32_t* b) {
    asm volatile(
        "mma.sync.aligned.m16n8k8.row.col.f32.tf32.tf32.f32 "
        "{%0,%1,%2,%3}, {%4,%5,%6,%7}, {%8,%9}, {%0,%1,%2,%3};"
        : "+f"(c[0]), "+f"(c[1]), "+f"(c[2]), "+f"(c[3])
        : "r"(a[0]), "r"(a[1]), "r"(a[2]), "r"(a[3]), "r"(b[0]), "r"(b[1]));
}

__device__ __forceinline__ void cp_async16(uint32_t saddr, const void* gaddr) {
    asm volatile("cp.async.cg.shared.global [%0], [%1], 16;"
                 :: "r"(saddr), "l"(gaddr) : "memory");
}

__global__ __launch_bounds__(256) void gemm_mma(
    const float* __restrict__ A, const float* __restrict__ Bm,
    float* __restrict__ C, int M, int N, int K)
{
    extern __shared__ float sdyn[];
    const uint32_t sbase = (uint32_t)__cvta_generic_to_shared(sdyn);

    const int tid  = threadIdx.x;
    const int wid  = tid >> 5;
    const int lane = tid & 31;
    const int warp_m = wid >> 2;          // 0..1
    const int warp_n = wid & 3;           // 0..3
    const int lane4 = lane >> 2;          // 0..7
    const int lanek = lane & 3;           // 0..3
    const int m0 = blockIdx.y * GBM;
    const int n0 = blockIdx.x * GBN;
    const int NK = K >> 4;                // BK=16 tiles

    // Global->smem mapping: row r = tid/2, two 16B chunks
    const int r  = tid >> 1;
    const int c0 = (tid & 1) * 2;         // chunk index 0/2
    const float* Ag = A  + (size_t)(m0 + r) * K;
    const float* Bg = Bm + (size_t)(n0 + r) * K;
    const uint32_t sArow = sbase + (uint32_t)r * (GSTRIDE * 4);
    const uint32_t sBrow = sArow + G_TILE_FLOATS * 4;

    // Prologue: fill 3 stages
#pragma unroll
    for (int s = 0; s < G_NSTAGE; s++) {
        uint32_t so = (uint32_t)s * (G_STAGE_FLOATS * 4);
        const float* ag = Ag + s * GBK;
        const float* bg = Bg + s * GBK;
        cp_async16(sArow + so + (c0    ) * 16, ag + (c0    ) * 4);
        cp_async16(sArow + so + (c0 + 1) * 16, ag + (c0 + 1) * 4);
        cp_async16(sBrow + so + (c0    ) * 16, bg + (c0    ) * 4);
        cp_async16(sBrow + so + (c0 + 1) * 16, bg + (c0 + 1) * 4);
        asm volatile("cp.async.commit_group;" ::: "memory");
    }

    float acc[4][4][4];
#pragma unroll
    for (int i = 0; i < 4; i++)
#pragma unroll
        for (int j = 0; j < 4; j++)
#pragma unroll
            for (int t = 0; t < 4; t++) acc[i][j][t] = 0.f;

    for (int it = 0; it < NK; it++) {
        asm volatile("cp.async.wait_group %0;" :: "n"(G_NSTAGE - 1) : "memory");
        __syncthreads();

        const float* sA = sdyn + (it % G_NSTAGE) * G_STAGE_FLOATS;
        const float* sB = sA + G_TILE_FLOATS;

#pragma unroll
        for (int ks = 0; ks < 2; ks++) {
            const int kb = ks * 8 + lanek;
            uint32_t af[4][4], bf[4][2];
#pragma unroll
            for (int mt = 0; mt < 4; mt++) {
                const float* ap = sA + (warp_m * 64 + mt * 16 + lane4) * GSTRIDE + kb;
                af[mt][0] = f2tf32(ap[0]);
                af[mt][1] = f2tf32(ap[8 * GSTRIDE]);
                af[mt][2] = f2tf32(ap[4]);
                af[mt][3] = f2tf32(ap[8 * GSTRIDE + 4]);
            }
#pragma unroll
            for (int nt = 0; nt < 4; nt++) {
                const float* bp = sB + (warp_n * 32 + nt * 8 + lane4) * GSTRIDE + kb;
                bf[nt][0] = f2tf32(bp[0]);
                bf[nt][1] = f2tf32(bp[4]);
            }
#pragma unroll
            for (int mt = 0; mt < 4; mt++)
#pragma unroll
                for (int nt = 0; nt < 4; nt++)
                    mma_tf32(acc[mt][nt], af[mt], bf[nt]);
        }

        __syncthreads();   // all warps done reading this stage

        int itn = it + G_NSTAGE;
        if (itn < NK) {
            uint32_t so = (uint32_t)(itn % G_NSTAGE) * (G_STAGE_FLOATS * 4);
            const float* ag = Ag + itn * GBK;
            const float* bg = Bg + itn * GBK;
            cp_async16(sArow + so + (c0    ) * 16, ag + (c0    ) * 4);
            cp_async16(sArow + so + (c0 + 1) * 16, ag + (c0 + 1) * 4);
            cp_async16(sBrow + so + (c0    ) * 16, bg + (c0    ) * 4);
            cp_async16(sBrow + so + (c0 + 1) * 16, bg + (c0 + 1) * 4);
        }
        asm volatile("cp.async.commit_group;" ::: "memory");
    }

    // Epilogue: direct float2 stores.
    // c0,c1 -> row lane/4,    cols 2*(lane%4)+{0,1}
    // c2,c3 -> row lane/4+8,  same cols
#pragma unroll
    for (int mt = 0; mt < 4; mt++) {
#pragma unroll
        for (int nt = 0; nt < 4; nt++) {
            int row = m0 + warp_m * 64 + mt * 16 + lane4;
            int col = n0 + warp_n * 32 + nt * 8 + lanek * 2;
            *(float2*)&C[(size_t)row * N + col] =
                make_float2(acc[mt][nt][0], acc[mt][nt][1]);
            *(float2*)&C[(size_t)(row + 8) * N + col] =
                make_float2(acc[mt][nt][2], acc[mt][nt][3]);
        }
    }
}

// ---------------------------------------------------------------------------
// RoPE + per-head RMSNorm + scatter into q/k/v attention layouts.
// ---------------------------------------------------------------------------
__global__ __launch_bounds__(128) void rope_norm(
    const float* __restrict__ cosb, const float* __restrict__ sinb,
    const float* __restrict__ qw,   const float* __restrict__ kw)
{
    int tok = blockIdx.y;
    int hh  = blockIdx.x;
    int d   = threadIdx.x;
    int b = tok / S_, s = tok % S_;
    const float* row = g_qkv + (size_t)tok * QKVN;

    if (hh >= H_ + KVH_) {                    // V: straight copy
        int kv = hh - (H_ + KVH_);
        g_v[(((size_t)b * KVH_ + kv) * S_ + s) * D_ + d] =
            row[H_ * D_ + KVH_ * D_ + kv * D_ + d];
        return;
    }

    float c  = cosb[((size_t)b * S_ + s) * D_ + d];
    float sn = sinb[((size_t)b * S_ + s) * D_ + d];
    int off = (hh < H_) ? hh * D_ : H_ * D_ + (hh - H_) * D_;
    float x  = row[off + d];
    float xr = (d < 64) ? -row[off + d + 64] : row[off + d - 64];
    float y  = x * c + xr * sn;

    float v2 = y * y;
#pragma unroll
    for (int o = 16; o; o >>= 1) v2 += __shfl_xor_sync(0xffffffffu, v2, o);
    __shared__ float red[4];
    if ((d & 31) == 0) red[d >> 5] = v2;
    __syncthreads();
    float tot = red[0] + red[1] + red[2] + red[3];
    float inv = rsqrtf(tot * (1.f / D_) + 1e-6f);
    float w = (hh < H_) ? qw[d] : kw[d];
    float outv = w * y * inv;

    if (hh < H_)
        g_q[(((size_t)b * H_ + hh) * S_ + s) * D_ + d] = outv;
    else
        g_k[(((size_t)b * KVH_ + (hh - H_)) * S_ + s) * D_ + d] = outv;
}

// ---------------------------------------------------------------------------
// Flash attention (fp32, non-causal, online softmax).
// ---------------------------------------------------------------------------
#define BR 64
#define BC 64
#define DP 132
#define PP 68
#define ATTN_SMEM ((3 * BR * DP + BR * PP) * 4)

__global__ __launch_bounds__(256) void flash_attn(float* __restrict__ AO)
{
    extern __shared__ float sm[];
    float* sQ = sm;
    float* sK = sQ + BR * DP;
    float* sV = sK + BC * DP;
    float* sP = sV + BC * DP;

    int b  = blockIdx.z, h = blockIdx.y;
    int q0 = blockIdx.x * BR;
    int kh = h / NREP;
    const float* Qg = g_q + (((size_t)b * H_ + h) * S_ + q0) * D_;
    const float* Kg = g_k + ((size_t)b * KVH_ + kh) * (size_t)S_ * D_;
    const float* Vg = g_v + ((size_t)b * KVH_ + kh) * (size_t)S_ * D_;

    int tid = threadIdx.x;
    int i  = tid >> 2;
    int jq = tid & 3;

    for (int e = tid; e < BR * 32; e += 256) {
        int r = e >> 5, c = e & 31;
        float4 v = ((const float4*)Qg)[r * 32 + c];
        *(float4*)&sQ[r * DP + c * 4] = v;
    }

    float acc[32];
#pragma unroll
    for (int t = 0; t < 32; t++) acc[t] = 0.f;
    float m_i = -1e30f, l_i = 0.f;
    const float scale = 0.08838834764831845f;

    for (int t0 = 0; t0 < S_; t0 += BC) {
        __syncthreads();
        for (int e = tid; e < BC * 32; e += 256) {
            int r = e >> 5, c = e & 31;
            *(float4*)&sK[r * DP + c * 4] = ((const float4*)(Kg + (size_t)t0 * D_))[r * 32 + c];
            *(float4*)&sV[r * DP + c * 4] = ((const float4*)(Vg + (size_t)t0 * D_))[r * 32 + c];
        }
        __syncthreads();

        float sc[16];
#pragma unroll
        for (int jj = 0; jj < 16; jj++) sc[jj] = 0.f;
#pragma unroll 4
        for (int d4 = 0; d4 < 32; d4++) {
            float4 qv = *(const float4*)&sQ[i * DP + d4 * 4];
#pragma unroll
            for (int jj = 0; jj < 16; jj++) {
                int j = jj * 4 + jq;
                float4 kv = *(const float4*)&sK[j * DP + d4 * 4];
                sc[jj] += qv.x * kv.x + qv.y * kv.y + qv.z * kv.z + qv.w * kv.w;
            }
        }

        float mt = -1e30f;
#pragma unroll
        for (int jj = 0; jj < 16; jj++) { sc[jj] *= scale; mt = fmaxf(mt, sc[jj]); }
        mt = fmaxf(mt, __shfl_xor_sync(0xffffffffu, mt, 1));
        mt = fmaxf(mt, __shfl_xor_sync(0xffffffffu, mt, 2));
        float m_new = fmaxf(m_i, mt);
        float corr = __expf(m_i - m_new);

        float ls = 0.f;
#pragma unroll
        for (int jj = 0; jj < 16; jj++) {
            float p = __expf(sc[jj] - m_new);
            ls += p;
            sP[i * PP + jj * 4 + jq] = p;
        }
        ls += __shfl_xor_sync(0xffffffffu, ls, 1);
        ls += __shfl_xor_sync(0xffffffffu, ls, 2);
        l_i = l_i * corr + ls;
        m_i = m_new;
#pragma unroll
        for (int t = 0; t < 32; t++) acc[t] *= corr;
        __syncthreads();

#pragma unroll 2
        for (int j = 0; j < BC; j++) {
            float pv = sP[i * PP + j];
            const float4* vr = (const float4*)&sV[j * DP + jq * 4];
#pragma unroll
            for (int g = 0; g < 8; g++) {
                float4 vv = vr[g * 4];
                acc[g * 4 + 0] += pv * vv.x;
                acc[g * 4 + 1] += pv * vv.y;
                acc[g * 4 + 2] += pv * vv.z;
                acc[g * 4 + 3] += pv * vv.w;
            }
        }
    }

    float inv = 1.f / l_i;
    float* Og = AO + (((size_t)(b * S_ + q0 + i)) * H_ + h) * (size_t)D_;
#pragma unroll
    for (int g = 0; g < 8; g++) {
        float4 o = make_float4(acc[g * 4 + 0] * inv, acc[g * 4 + 1] * inv,
                               acc[g * 4 + 2] * inv, acc[g * 4 + 3] * inv);
        *(float4*)&Og[g * 16 + jq * 4] = o;
    }
}

// ---------------------------------------------------------------------------
extern "C" void kernel_launch(void* const* d_in, const int* in_sizes, int n_in,
                              void* d_out, int out_size)
{
    const float* hidden = (const float*)d_in[0];
    const float* cosb   = (const float*)d_in[1];
    const float* sinb   = (const float*)d_in[2];
    const float* qkv_w  = (const float*)d_in[3];
    const float* o_w    = (const float*)d_in[4];
    const float* qnw    = (const float*)d_in[5];
    const float* knw    = (const float*)d_in[6];
    float* out = (float*)d_out;

    float *qkvp, *aop;
    cudaGetSymbolAddress((void**)&qkvp, g_qkv);
    cudaGetSymbolAddress((void**)&aop,  g_ao);

    cudaFuncSetAttribute(gemm_mma, cudaFuncAttributeMaxDynamicSharedMemorySize,
                         G_DYN_SMEM);
    cudaFuncSetAttribute(flash_attn, cudaFuncAttributeMaxDynamicSharedMemorySize,
                         ATTN_SMEM);

    // 1) QKV projection: [4096,6144] = hidden @ qkv_w^T   (tf32 mma.sync)
    dim3 g1(QKVN / 128, MTOK / 128);
    gemm_mma<<<g1, 256, G_DYN_SMEM>>>(hidden, qkv_w, qkvp, MTOK, QKVN, HID_);

    // 2) RoPE + RMSNorm + layout scatter
    dim3 g2(H_ + 2 * KVH_, MTOK);
    rope_norm<<<g2, 128>>>(cosb, sinb, qnw, knw);

    // 3) Attention (fp32 flash)
    dim3 g3(S_ / BR, H_, B_);
    flash_attn<<<g3, 256, ATTN_SMEM>>>(aop);

    // 4) O projection: [4096,4096] = AO @ o_w^T   (tf32 mma.sync)
    dim3 g4(HID_ / 128, MTOK / 128);
    gemm_mma<<<g4, 256, G_DYN_SMEM>>>(aop, o_w, out, MTOK, HID_, H_ * D_);
}

// round 4
// speedup vs baseline: 3.0937x; 2.2530x over previous
#include <cuda_runtime.h>
#include <cstdint>
#include <math.h>

// Problem constants
#define B_    2
#define S_    2048
#define HID_  4096
#define H_    32
#define KVH_  8
#define D_    128
#define NREP  (H_/KVH_)                 // 4
#define QKVN  (HID_ + 2*KVH_*D_)        // 6144
#define MTOK  (B_*S_)                   // 4096

// Scratch (static device globals; no runtime allocation allowed)
__device__ float g_qkv[(size_t)MTOK * QKVN];            // [tok][6144]
__device__ float g_q  [(size_t)B_*H_*S_*D_];            // [B][H][S][D]
__device__ float g_k  [(size_t)B_*KVH_*S_*D_];          // [B][KVH][S][D]
__device__ float g_v  [(size_t)B_*KVH_*S_*D_];          // [B][KVH][S][D]
__device__ float g_ao [(size_t)MTOK * H_*D_];           // [B][S][H][D]

__device__ __forceinline__ uint32_t f2tf32(float f) {
    uint32_t r;
    asm("cvt.rna.tf32.f32 %0, %1;" : "=r"(r) : "f"(f));
    return r;
}
__device__ __forceinline__ float ex2f(float x) {
    float y;
    asm("ex2.approx.f32 %0, %1;" : "=f"(y) : "f"(x));
    return y;
}
__device__ __forceinline__ void mma_tf32(float* c, const uint32_t* a, const uint32_t* b) {
    asm volatile(
        "mma.sync.aligned.m16n8k8.row.col.f32.tf32.tf32.f32 "
        "{%0,%1,%2,%3}, {%4,%5,%6,%7}, {%8,%9}, {%0,%1,%2,%3};"
        : "+f"(c[0]), "+f"(c[1]), "+f"(c[2]), "+f"(c[3])
        : "r"(a[0]), "r"(a[1]), "r"(a[2]), "r"(a[3]), "r"(b[0]), "r"(b[1]));
}
__device__ __forceinline__ void cp_async16(uint32_t saddr, const void* gaddr) {
    asm volatile("cp.async.cg.shared.global [%0], [%1], 16;"
                 :: "r"(saddr), "l"(gaddr) : "memory");
}

// ===========================================================================
// tf32 mma.sync GEMM (NT): C[M,N] = A[M,K] * B[N,K]^T, fp32 in/out.
// 128x128 CTA tile, BK=16, 8 warps (2x4), 64x32 warp tile, 3-stage cp.async.
// ===========================================================================
#define GBM 128
#define GBN 128
#define GBK 16
#define GSTRIDE 20
#define G_TILE_FLOATS (128 * GSTRIDE)
#define G_STAGE_FLOATS (2 * G_TILE_FLOATS)
#define G_NSTAGE 3
#define G_DYN_SMEM (G_NSTAGE * G_STAGE_FLOATS * 4)

__global__ __launch_bounds__(256) void gemm_mma(
    const float* __restrict__ A, const float* __restrict__ Bm,
    float* __restrict__ C, int M, int N, int K)
{
    extern __shared__ float sdyn[];
    const uint32_t sbase = (uint32_t)__cvta_generic_to_shared(sdyn);

    const int tid  = threadIdx.x;
    const int wid  = tid >> 5;
    const int lane = tid & 31;
    const int warp_m = wid >> 2;
    const int warp_n = wid & 3;
    const int lane4 = lane >> 2;
    const int lanek = lane & 3;
    const int m0 = blockIdx.y * GBM;
    const int n0 = blockIdx.x * GBN;
    const int NK = K >> 4;

    const int r  = tid >> 1;
    const int c0 = (tid & 1) * 2;
    const float* Ag = A  + (size_t)(m0 + r) * K;
    const float* Bg = Bm + (size_t)(n0 + r) * K;
    const uint32_t sArow = sbase + (uint32_t)r * (GSTRIDE * 4);
    const uint32_t sBrow = sArow + G_TILE_FLOATS * 4;

#pragma unroll
    for (int s = 0; s < G_NSTAGE; s++) {
        uint32_t so = (uint32_t)s * (G_STAGE_FLOATS * 4);
        const float* ag = Ag + s * GBK;
        const float* bg = Bg + s * GBK;
        cp_async16(sArow + so + (c0    ) * 16, ag + (c0    ) * 4);
        cp_async16(sArow + so + (c0 + 1) * 16, ag + (c0 + 1) * 4);
        cp_async16(sBrow + so + (c0    ) * 16, bg + (c0    ) * 4);
        cp_async16(sBrow + so + (c0 + 1) * 16, bg + (c0 + 1) * 4);
        asm volatile("cp.async.commit_group;" ::: "memory");
    }

    float acc[4][4][4];
#pragma unroll
    for (int i = 0; i < 4; i++)
#pragma unroll
        for (int j = 0; j < 4; j++)
#pragma unroll
            for (int t = 0; t < 4; t++) acc[i][j][t] = 0.f;

    for (int it = 0; it < NK; it++) {
        asm volatile("cp.async.wait_group %0;" :: "n"(G_NSTAGE - 1) : "memory");
        __syncthreads();

        const float* sA = sdyn + (it % G_NSTAGE) * G_STAGE_FLOATS;
        const float* sB = sA + G_TILE_FLOATS;

#pragma unroll
        for (int ks = 0; ks < 2; ks++) {
            const int kb = ks * 8 + lanek;
            uint32_t af[4][4], bf[4][2];
#pragma unroll
            for (int mt = 0; mt < 4; mt++) {
                const float* ap = sA + (warp_m * 64 + mt * 16 + lane4) * GSTRIDE + kb;
                af[mt][0] = f2tf32(ap[0]);
                af[mt][1] = f2tf32(ap[8 * GSTRIDE]);
                af[mt][2] = f2tf32(ap[4]);
                af[mt][3] = f2tf32(ap[8 * GSTRIDE + 4]);
            }
#pragma unroll
            for (int nt = 0; nt < 4; nt++) {
                const float* bp = sB + (warp_n * 32 + nt * 8 + lane4) * GSTRIDE + kb;
                bf[nt][0] = f2tf32(bp[0]);
                bf[nt][1] = f2tf32(bp[4]);
            }
#pragma unroll
            for (int mt = 0; mt < 4; mt++)
#pragma unroll
                for (int nt = 0; nt < 4; nt++)
                    mma_tf32(acc[mt][nt], af[mt], bf[nt]);
        }

        __syncthreads();

        int itn = it + G_NSTAGE;
        if (itn < NK) {
            uint32_t so = (uint32_t)(itn % G_NSTAGE) * (G_STAGE_FLOATS * 4);
            const float* ag = Ag + itn * GBK;
            const float* bg = Bg + itn * GBK;
            cp_async16(sArow + so + (c0    ) * 16, ag + (c0    ) * 4);
            cp_async16(sArow + so + (c0 + 1) * 16, ag + (c0 + 1) * 4);
            cp_async16(sBrow + so + (c0    ) * 16, bg + (c0    ) * 4);
            cp_async16(sBrow + so + (c0 + 1) * 16, bg + (c0 + 1) * 4);
        }
        asm volatile("cp.async.commit_group;" ::: "memory");
    }

#pragma unroll
    for (int mt = 0; mt < 4; mt++) {
#pragma unroll
        for (int nt = 0; nt < 4; nt++) {
            int row = m0 + warp_m * 64 + mt * 16 + lane4;
            int col = n0 + warp_n * 32 + nt * 8 + lanek * 2;
            *(float2*)&C[(size_t)row * N + col] =
                make_float2(acc[mt][nt][0], acc[mt][nt][1]);
            *(float2*)&C[(size_t)(row + 8) * N + col] =
                make_float2(acc[mt][nt][2], acc[mt][nt][3]);
        }
    }
}

// ---------------------------------------------------------------------------
// RoPE + per-head RMSNorm + scatter into q/k/v attention layouts.
// ---------------------------------------------------------------------------
__global__ __launch_bounds__(128) void rope_norm(
    const float* __restrict__ cosb, const float* __restrict__ sinb,
    const float* __restrict__ qw,   const float* __restrict__ kw)
{
    int tok = blockIdx.y;
    int hh  = blockIdx.x;
    int d   = threadIdx.x;
    int b = tok / S_, s = tok % S_;
    const float* row = g_qkv + (size_t)tok * QKVN;

    if (hh >= H_ + KVH_) {
        int kv = hh - (H_ + KVH_);
        g_v[(((size_t)b * KVH_ + kv) * S_ + s) * D_ + d] =
            row[H_ * D_ + KVH_ * D_ + kv * D_ + d];
        return;
    }

    float c  = cosb[((size_t)b * S_ + s) * D_ + d];
    float sn = sinb[((size_t)b * S_ + s) * D_ + d];
    int off = (hh < H_) ? hh * D_ : H_ * D_ + (hh - H_) * D_;
    float x  = row[off + d];
    float xr = (d < 64) ? -row[off + d + 64] : row[off + d - 64];
    float y  = x * c + xr * sn;

    float v2 = y * y;
#pragma unroll
    for (int o = 16; o; o >>= 1) v2 += __shfl_xor_sync(0xffffffffu, v2, o);
    __shared__ float red[4];
    if ((d & 31) == 0) red[d >> 5] = v2;
    __syncthreads();
    float tot = red[0] + red[1] + red[2] + red[3];
    float inv = rsqrtf(tot * (1.f / D_) + 1e-6f);
    float w = (hh < H_) ? qw[d] : kw[d];
    float outv = w * y * inv;

    if (hh < H_)
        g_q[(((size_t)b * H_ + hh) * S_ + s) * D_ + d] = outv;
    else
        g_k[(((size_t)b * KVH_ + (hh - H_)) * S_ + s) * D_ + d] = outv;
}

// ---------------------------------------------------------------------------
// Flash attention with tf32 mma.sync. BR=BC=64, D=128, 128 threads (4 warps).
// Warp w owns rows 16w..16w+15. Q/K/V staged in smem pre-converted to tf32.
// Scores & softmax live in mma C-fragment layout; P round-trips through
// per-warp smem to become the next A fragment.
// ---------------------------------------------------------------------------
#define ADP 132    // Q/K/V smem row stride (floats)
#define APP 68     // P smem row stride (floats)
#define ATTN_SMEM ((3 * 64 * ADP + 4 * 16 * APP) * 4)   // 118784 bytes

__global__ __launch_bounds__(128) void flash_attn_mma(float* __restrict__ AO)
{
    extern __shared__ float sm[];
    float* sQ = sm;                    // 64 x 132 (tf32 bits, pre-scaled)
    float* sK = sQ + 64 * ADP;         // 64 x 132 (tf32 bits)
    float* sV = sK + 64 * ADP;         // 64 x 132 (tf32 bits)
    float* sP = sV + 64 * ADP;         // 4 warps x 16 x 68 (tf32 bits)

    const int b  = blockIdx.z, h = blockIdx.y;
    const int q0 = blockIdx.x * 64;
    const int kh = h / NREP;
    const float* Qg = g_q + (((size_t)b * H_ + h) * S_ + q0) * D_;
    const float* Kg = g_k + ((size_t)b * KVH_ + kh) * (size_t)S_ * D_;
    const float* Vg = g_v + ((size_t)b * KVH_ + kh) * (size_t)S_ * D_;

    const int tid  = threadIdx.x;
    const int w    = tid >> 5;
    const int lane = tid & 31;
    const int lane4 = lane >> 2;     // 0..7
    const int lanek = lane & 3;      // 0..3

    // scale * log2(e), folded into Q so scores are in log2 domain
    const float QSC = 0.08838834764831845f * 1.4426950408889634f;

    // Load Q tile, scale, convert to tf32
    for (int e = tid; e < 64 * 32; e += 128) {
        int r = e >> 5, c = e & 31;
        float4 v = ((const float4*)Qg)[r * 32 + c];
        uint4 u;
        u.x = f2tf32(v.x * QSC); u.y = f2tf32(v.y * QSC);
        u.z = f2tf32(v.z * QSC); u.w = f2tf32(v.w * QSC);
        *(uint4*)&sQ[r * ADP + c * 4] = u;
    }

    float oacc[16][4];
#pragma unroll
    for (int nt = 0; nt < 16; nt++)
#pragma unroll
        for (int t = 0; t < 4; t++) oacc[nt][t] = 0.f;
    float m0 = -1e30f, m1 = -1e30f, l0 = 0.f, l1 = 0.f;

    const uint32_t* sQu = (const uint32_t*)sQ;
    const uint32_t* sKu = (const uint32_t*)sK;
    const uint32_t* sVu = (const uint32_t*)sV;
    uint32_t* sPw = (uint32_t*)sP + w * (16 * APP);

    for (int t0 = 0; t0 < S_; t0 += 64) {
        __syncthreads();   // prev iteration's sK/sV reads done
        for (int e = tid; e < 64 * 32; e += 128) {
            int r = e >> 5, c = e & 31;
            float4 kv = ((const float4*)(Kg + (size_t)t0 * D_))[r * 32 + c];
            float4 vv = ((const float4*)(Vg + (size_t)t0 * D_))[r * 32 + c];
            uint4 ku, vu;
            ku.x = f2tf32(kv.x); ku.y = f2tf32(kv.y);
            ku.z = f2tf32(kv.z); ku.w = f2tf32(kv.w);
            vu.x = f2tf32(vv.x); vu.y = f2tf32(vv.y);
            vu.z = f2tf32(vv.z); vu.w = f2tf32(vv.w);
            *(uint4*)&sK[r * ADP + c * 4] = ku;
            *(uint4*)&sV[r * ADP + c * 4] = vu;
        }
        __syncthreads();

        // ---- QK^T: scores sc[nt][.], rows (16w+lane4, +8), cols nt*8+2*lanek+{0,1}
        float sc[8][4];
#pragma unroll
        for (int nt = 0; nt < 8; nt++)
#pragma unroll
            for (int t = 0; t < 4; t++) sc[nt][t] = 0.f;

#pragma unroll
        for (int kk = 0; kk < 16; kk++) {
            uint32_t a[4];
            const uint32_t* qp = sQu + (w * 16 + lane4) * ADP + kk * 8 + lanek;
            a[0] = qp[0]; a[1] = qp[8 * ADP]; a[2] = qp[4]; a[3] = qp[8 * ADP + 4];
#pragma unroll
            for (int nt = 0; nt < 8; nt++) {
                uint32_t bb[2];
                const uint32_t* kp = sKu + (nt * 8 + lane4) * ADP + kk * 8 + lanek;
                bb[0] = kp[0]; bb[1] = kp[4];
                mma_tf32(sc[nt], a, bb);
            }
        }

        // ---- online softmax (log2 domain)
        float mx0 = -1e30f, mx1 = -1e30f;
#pragma unroll
        for (int nt = 0; nt < 8; nt++) {
            mx0 = fmaxf(mx0, fmaxf(sc[nt][0], sc[nt][1]));
            mx1 = fmaxf(mx1, fmaxf(sc[nt][2], sc[nt][3]));
        }
        mx0 = fmaxf(mx0, __shfl_xor_sync(0xffffffffu, mx0, 1));
        mx0 = fmaxf(mx0, __shfl_xor_sync(0xffffffffu, mx0, 2));
        mx1 = fmaxf(mx1, __shfl_xor_sync(0xffffffffu, mx1, 1));
        mx1 = fmaxf(mx1, __shfl_xor_sync(0xffffffffu, mx1, 2));
        float mn0 = fmaxf(m0, mx0), mn1 = fmaxf(m1, mx1);
        float cr0 = ex2f(m0 - mn0), cr1 = ex2f(m1 - mn1);

        float s0 = 0.f, s1 = 0.f;
#pragma unroll
        for (int nt = 0; nt < 8; nt++) {
            float p00 = ex2f(sc[nt][0] - mn0);
            float p01 = ex2f(sc[nt][1] - mn0);
            float p10 = ex2f(sc[nt][2] - mn1);
            float p11 = ex2f(sc[nt][3] - mn1);
            s0 += p00 + p01;
            s1 += p10 + p11;
            uint2 lo = make_uint2(f2tf32(p00), f2tf32(p01));
            uint2 hi = make_uint2(f2tf32(p10), f2tf32(p11));
            *(uint2*)&sPw[lane4 * APP + nt * 8 + 2 * lanek]       = lo;
            *(uint2*)&sPw[(lane4 + 8) * APP + nt * 8 + 2 * lanek] = hi;
        }
        s0 += __shfl_xor_sync(0xffffffffu, s0, 1);
        s0 += __shfl_xor_sync(0xffffffffu, s0, 2);
        s1 += __shfl_xor_sync(0xffffffffu, s1, 1);
        s1 += __shfl_xor_sync(0xffffffffu, s1, 2);
        l0 = l0 * cr0 + s0;
        l1 = l1 * cr1 + s1;
        m0 = mn0; m1 = mn1;

#pragma unroll
        for (int nt = 0; nt < 16; nt++) {
            oacc[nt][0] *= cr0; oacc[nt][1] *= cr0;
            oacc[nt][2] *= cr1; oacc[nt][3] *= cr1;
        }
        __syncwarp();   // sP visible within warp

        // ---- P @ V: k-dim = key (64), n-dim = d (128)
#pragma unroll
        for (int kk = 0; kk < 8; kk++) {
            uint32_t a[4];
            const uint32_t* pp = sPw + lane4 * APP + kk * 8 + lanek;
            a[0] = pp[0]; a[1] = pp[8 * APP]; a[2] = pp[4]; a[3] = pp[8 * APP + 4];
#pragma unroll
            for (int nt = 0; nt < 16; nt++) {
                uint32_t bb[2];
                const uint32_t* vp = sVu + (kk * 8 + lanek) * ADP + nt * 8 + lane4;
                bb[0] = vp[0]; bb[1] = vp[4 * ADP];
                mma_tf32(oacc[nt], a, bb);
            }
        }
        __syncwarp();   // PV reads of sP done before next tile overwrites
    }

    float i0 = 1.f / l0, i1 = 1.f / l1;
    int row0 = q0 + w * 16 + lane4;
    float* O0 = AO + ((size_t)(b * S_ + row0) * H_ + h) * D_;
    float* O1 = O0 + (size_t)8 * H_ * D_;
#pragma unroll
    for (int nt = 0; nt < 16; nt++) {
        int col = nt * 8 + 2 * lanek;
        *(float2*)&O0[col] = make_float2(oacc[nt][0] * i0, oacc[nt][1] * i0);
        *(float2*)&O1[col] = make_float2(oacc[nt][2] * i1, oacc[nt][3] * i1);
    }
}

// ---------------------------------------------------------------------------
extern "C" void kernel_launch(void* const* d_in, const int* in_sizes, int n_in,
                              void* d_out, int out_size)
{
    const float* hidden = (const float*)d_in[0];
    const float* cosb   = (const float*)d_in[1];
    const float* sinb   = (const float*)d_in[2];
    const float* qkv_w  = (const float*)d_in[3];
    const float* o_w    = (const float*)d_in[4];
    const float* qnw    = (const float*)d_in[5];
    const float* knw    = (const float*)d_in[6];
    float* out = (float*)d_out;

    float *qkvp, *aop;
    cudaGetSymbolAddress((void**)&qkvp, g_qkv);
    cudaGetSymbolAddress((void**)&aop,  g_ao);

    cudaFuncSetAttribute(gemm_mma, cudaFuncAttributeMaxDynamicSharedMemorySize,
                         G_DYN_SMEM);
    cudaFuncSetAttribute(flash_attn_mma, cudaFuncAttributeMaxDynamicSharedMemorySize,
                         ATTN_SMEM);

    // 1) QKV projection (tf32 mma.sync)
    dim3 g1(QKVN / 128, MTOK / 128);
    gemm_mma<<<g1, 256, G_DYN_SMEM>>>(hidden, qkv_w, qkvp, MTOK, QKVN, HID_);

    // 2) RoPE + RMSNorm + layout scatter
    dim3 g2(H_ + 2 * KVH_, MTOK);
    rope_norm<<<g2, 128>>>(cosb, sinb, qnw, knw);

    // 3) Attention (tf32 mma.sync flash)
    dim3 g3(S_ / 64, H_, B_);
    flash_attn_mma<<<g3, 128, ATTN_SMEM>>>(aop);

    // 4) O projection (tf32 mma.sync)
    dim3 g4(HID_ / 128, MTOK / 128);
    gemm_mma<<<g4, 256, G_DYN_SMEM>>>(aop, o_w, out, MTOK, HID_, H_ * D_);
}